// round 10
// baseline (speedup 1.0000x reference)
#include <cuda_runtime.h>

#define IMG 512
#define BATCH 32
#define TW 128
#define TH 16
#define RAD 5
#define RAW_W 138        // TW + 2*RAD columns needed by stage 2
#define RS 140           // vbuf col count per half-row (floats); even, mult of 4
#define PLANE (16 * RS)  // floats per plane: 8 yp-rows * RS cols * 2 lanes
#define NTHREADS 256
#define NBLOCKS 4096     // (512/128) * (512/16) * 32
#define NPIX_D 8388608.0
#define G 4              // stage-1 vertical row-group size
#define NSLOTS1 (4 * RAW_W)   // 552 stage-1 slots
#define JROWS (G + 10)        // 14 raw rows feed 4 output rows

typedef unsigned long long u64;

__device__ double g_accum;          // zero-initialized at module load
__device__ unsigned int g_count;    // zero-initialized at module load

// ---- f32x2 packed-math helpers; operands come pre-packed from LDS.128 ----
__device__ __forceinline__ u64 pk2(float lo, float hi) {
    u64 r; asm("mov.b64 %0, {%1, %2};" : "=l"(r) : "f"(lo), "f"(hi)); return r;
}
__device__ __forceinline__ void upk2(u64 v, float& lo, float& hi) {
    asm("mov.b64 {%0, %1}, %2;" : "=f"(lo), "=f"(hi) : "l"(v));
}
__device__ __forceinline__ u64 fma2_(u64 a, u64 b, u64 c) {
    u64 d; asm("fma.rn.f32x2 %0, %1, %2, %3;" : "=l"(d) : "l"(a), "l"(b), "l"(c)); return d;
}
__device__ __forceinline__ u64 mul2_(u64 a, u64 b) {
    u64 d; asm("mul.rn.f32x2 %0, %1, %2;" : "=l"(d) : "l"(a), "l"(b)); return d;
}
__device__ __forceinline__ u64 add2_(u64 a, u64 b) {
    u64 d; asm("add.rn.f32x2 %0, %1, %2;" : "=l"(d) : "l"(a), "l"(b)); return d;
}

// Normalized 1-D Gaussian, sigma=1.5, K=11; symmetric W[d]=W[10-d]
__device__ __forceinline__ float wgt(int d) {
    const float WH[6] = {0.00102838f, 0.00759876f, 0.03600078f,
                         0.10936070f, 0.21300554f, 0.26601172f};
    return WH[d < 6 ? d : 10 - d];
}

// Horizontal 11-tap conv, 4 packed outputs, windows consumed streaming.
// rowf points at packed float2 elements: element j = {v(yp, x0+j), v(yp+8, x0+j)}.
__device__ __forceinline__ void hconv_pk(const float* __restrict__ rowf,
                                         const u64* __restrict__ Wp, u64 out[4]) {
    const ulonglong2* rp = (const ulonglong2*)rowf;
    out[0] = out[1] = out[2] = out[3] = 0ull;
    #pragma unroll
    for (int t = 0; t < 7; t++) {           // 7 x LDS.128 = 14 packed elements
        ulonglong2 v = rp[t];
        const int j0 = 2 * t, j1 = 2 * t + 1;
        #pragma unroll
        for (int o = 0; o < 4; o++) {
            const int d0 = j0 - o;
            if (d0 >= 0 && d0 < 11) out[o] = fma2_(Wp[d0 < 6 ? d0 : 10 - d0], v.x, out[o]);
            const int d1 = j1 - o;
            if (d1 >= 0 && d1 < 11) out[o] = fma2_(Wp[d1 < 6 ? d1 : 10 - d1], v.y, out[o]);
        }
    }
}

__global__ __launch_bounds__(NTHREADS, 4)
void ssim_main_kernel(const float* __restrict__ img1, const float* __restrict__ img2,
                      float* __restrict__ out) {
    extern __shared__ float sm[];
    // 5 planes, each PLANE floats, y-pair interleaved:
    //   plane p, element (yp, col): lane0 = v(yp,col), lane1 = v(yp+8,col)
    //   float index = p*PLANE + yp*(2*RS) + 2*col + lane
    float* red = sm + 5 * PLANE;        // 8 floats

    const int tid = threadIdx.x;
    const int bx0 = blockIdx.x * TW - RAD;
    const int by0 = blockIdx.y * TH - RAD;
    const long ib = (long)blockIdx.z * IMG * IMG;

    // ---- stage 1: vertical 11-tap conv of 5 quantities, scalar (as R6) ----
    for (int s = tid; s < NSLOTS1; s += NTHREADS) {
        int grp = s / RAW_W;
        int col = s - grp * RAW_W;          // 0..137
        int ybase = grp * G;
        int gx = bx0 + col;
        int gybase = by0 + ybase;
        const bool xin = (gx >= 0) & (gx < IMG);
        const float* p1 = img1 + ib + (long)gybase * IMG + gx;
        const float* p2 = img2 + ib + (long)gybase * IMG + gx;

        float acc0[G] = {0,0,0,0};
        float acc1[G] = {0,0,0,0};
        float acc2[G] = {0,0,0,0};
        float acc3[G] = {0,0,0,0};
        float acc4[G] = {0,0,0,0};
        #pragma unroll
        for (int j = 0; j < JROWS; j++) {
            int gy = gybase + j;
            bool in = xin & (gy >= 0) & (gy < IMG);
            float av = in ? p1[j * IMG] : 0.f;
            float bv = in ? p2[j * IMG] : 0.f;
            float aa = av * av, bb = bv * bv, ab = av * bv;
            #pragma unroll
            for (int o = 0; o < G; o++) {
                const int d = j - o;
                if (d >= 0 && d < 11) {
                    const float w = wgt(d);     // compile-time const -> FFMA-imm
                    acc0[o] += w * av;
                    acc1[o] += w * bv;
                    acc2[o] += w * aa;
                    acc3[o] += w * bb;
                    acc4[o] += w * ab;
                }
            }
        }
        #pragma unroll
        for (int o = 0; o < G; o++) {
            int row = ybase + o;
            int ypr  = row & 7;                 // uniform per slot after unroll
            int lane = row >> 3;
            int fi = ypr * (2 * RS) + 2 * col + lane;
            sm[0 * PLANE + fi] = acc0[o];
            sm[1 * PLANE + fi] = acc1[o];
            sm[2 * PLANE + fi] = acc2[o];
            sm[3 * PLANE + fi] = acc3[o];
            sm[4 * PLANE + fi] = acc4[o];
        }
    }
    __syncthreads();

    // ---- stage 2: horizontal conv, f32x2-packed across y-pair via layout ----
    u64 Wp[6];
    #pragma unroll
    for (int d = 0; d < 6; d++) { float w = wgt(d); Wp[d] = pk2(w, w); }

    float lsum = 0.f;
    {
        int xg = tid & 31;                  // 32 x-groups * 8 y-pairs = 256 slots
        int yp = tid >> 5;                  // rows yp and yp+8 (packed lanes)
        // float offset of packed element (yp, x0): x0 = xg*4
        const int fo = yp * (2 * RS) + xg * 8;   // 32B-aligned

        u64 m1[4], m2[4], mu12[4], musq[4], t23[4], r4[4];

        hconv_pk(sm + 0 * PLANE + fo, Wp, m1);
        hconv_pk(sm + 1 * PLANE + fo, Wp, m2);
        #pragma unroll
        for (int o = 0; o < 4; o++) {
            mu12[o] = mul2_(m1[o], m2[o]);
            musq[o] = fma2_(m2[o], m2[o], mul2_(m1[o], m1[o]));
        }
        hconv_pk(sm + 2 * PLANE + fo, Wp, t23);
        hconv_pk(sm + 3 * PLANE + fo, Wp, r4);
        #pragma unroll
        for (int o = 0; o < 4; o++) t23[o] = add2_(t23[o], r4[o]);
        hconv_pk(sm + 4 * PLANE + fo, Wp, r4);          // E[ab]

        const u64 NEG1 = pk2(-1.f, -1.f);
        const u64 C1v  = pk2(0.0001f, 0.0001f);
        const u64 C2v  = pk2(0.0009f, 0.0009f);
        #pragma unroll
        for (int o = 0; o < 4; o++) {
            u64 s12  = fma2_(mu12[o], NEG1, r4[o]);     // E[ab] - mu1*mu2
            u64 sigs = fma2_(musq[o], NEG1, t23[o]);    // s1 + s2
            u64 num  = mul2_(add2_(add2_(mu12[o], mu12[o]), C1v),
                             add2_(add2_(s12, s12), C2v));
            u64 den  = mul2_(add2_(musq[o], C1v), add2_(sigs, C2v));
            float n0, n1, d0, d1;
            upk2(num, n0, n1);
            upk2(den, d0, d1);
            lsum += __fdividef(n0, d0) + __fdividef(n1, d1);
        }
    }

    // ---- block reduction ----
    #pragma unroll
    for (int off = 16; off > 0; off >>= 1)
        lsum += __shfl_xor_sync(0xffffffff, lsum, off);
    if ((tid & 31) == 0) red[tid >> 5] = lsum;
    __syncthreads();

    // ---- single-kernel finalize ----
    if (tid == 0) {
        float v = red[0] + red[1] + red[2] + red[3] +
                  red[4] + red[5] + red[6] + red[7];
        atomicAdd(&g_accum, (double)v);
        __threadfence();
        unsigned int ticket = atomicAdd(&g_count, 1u);
        if (ticket == NBLOCKS - 1) {
            double sfin = atomicAdd(&g_accum, 0.0);
            out[0] = (float)(1.0 - sfin / NPIX_D);
            g_accum = 0.0;
            g_count = 0u;
        }
    }
}

extern "C" void kernel_launch(void* const* d_in, const int* in_sizes, int n_in,
                              void* d_out, int out_size) {
    const float* img1 = (const float*)d_in[0];
    const float* img2 = (const float*)d_in[1];
    float* out = (float*)d_out;

    const size_t smem = (size_t)(5 * PLANE + 8) * sizeof(float);   // ~44.9 KB
    cudaFuncSetAttribute(ssim_main_kernel,
                         cudaFuncAttributeMaxDynamicSharedMemorySize, (int)smem);

    dim3 grid(IMG / TW, IMG / TH, BATCH);   // 4 x 32 x 32 = 4096 blocks
    ssim_main_kernel<<<grid, NTHREADS, smem>>>(img1, img2, out);
}